// round 12
// baseline (speedup 1.0000x reference)
#include <cuda_runtime.h>
#include <cuda_fp16.h>
#include <math.h>
#include <stdint.h>

#define NN 8192
#define T 64
#define NT (NN / T)                 // 128
#define NPAIRS (NT * (NT + 1) / 2)  // 8256 upper-tri tile pairs

// 16B-granular XOR swizzle for fp32 tiles: phys_chunk = chunk ^ ((row>>2)&7).
#define SWZ(r) (((r) >> 2) & 7)

__device__ float g_part[NT][NN];          // per-slot partial rowsums (4 MB)
__device__ float g_d[NN];
__device__ __half g_m[(size_t)NPAIRS * T * T];   // fp16 m tiles, 64.5 MB

// ---------------------------------------------------------------------------
__device__ __forceinline__ void tri_decode(int t, int& bi, int& bj) {
    float a = 2.0f * NT + 1.0f;
    int b = (int)(0.5f * (a - sqrtf(a * a - 8.0f * (float)t)));
    if (b < 0) b = 0;
    if (b > NT - 1) b = NT - 1;
    while (b > 0 && (b * NT - b * (b - 1) / 2) > t) b--;
    while (((b + 1) * NT - (b + 1) * b / 2) <= t) b++;
    bi = b;
    bj = b + (t - (b * NT - b * (b - 1) / 2));
}

// cp.async with L2 evict-first policy: adj is read-once, keep it OUT of L2
// so the g_m write stream stays resident for pass2.
__device__ __forceinline__ uint64_t mk_evict_first() {
    uint64_t pol;
    asm("createpolicy.fractional.L2::evict_first.b64 %0, 1.0;" : "=l"(pol));
    return pol;
}
__device__ __forceinline__ void cp_async16_ef(uint32_t dst, const float* src, uint64_t pol) {
    asm volatile("cp.async.cg.shared.global.L2::cache_hint [%0], [%1], 16, %2;"
                 :: "r"(dst), "l"(src), "l"(pol));
}
__device__ __forceinline__ void cp_commit() {
    asm volatile("cp.async.commit_group;" ::: "memory");
}
__device__ __forceinline__ void cp_wait0() {
    asm volatile("cp.async.wait_group 0;" ::: "memory");
}

// Issue one 64x64 fp32 tile load: thread (g = tid>>4, c4 = tid&15) loads 4 rows.
__device__ __forceinline__ void load_tile(uint32_t sbase, const float* __restrict__ src,
                                          int g, int c4, uint64_t pol) {
    #pragma unroll
    for (int k = 0; k < 4; k++) {
        int row = g + 16 * k;
        uint32_t dst = sbase + (uint32_t)((row * 64 + 4 * (c4 ^ SWZ(row))) * 4);
        cp_async16_ef(dst, src + (size_t)row * NN + 4 * c4, pol);
    }
}

// ---------------------------------------------------------------------------
// Pass 1 (identical to R9 best): m = max(adj, adjT); fp32 row+col partials;
// persist m as fp16 (normal stores, stays L2-resident); adj evict-first.
// ---------------------------------------------------------------------------
__global__ __launch_bounds__(256) void pass1_kernel(const float* __restrict__ adj) {
    __shared__ float s1[T * T];
    __shared__ float s2[T * T];
    __shared__ float rbuf[16][68];   // rbuf[c4][row]
    __shared__ float cbuf[16][68];   // cbuf[g][col]

    int t = blockIdx.x;
    int bi, bj;
    tri_decode(t, bi, bj);
    int tid = threadIdx.x;
    int c4 = tid & 15, g = tid >> 4;
    bool diag = (bi == bj);
    uint64_t pol = mk_evict_first();

    uint32_t s1a = (uint32_t)__cvta_generic_to_shared(s1);
    uint32_t s2a = (uint32_t)__cvta_generic_to_shared(s2);

    load_tile(s1a, adj + (size_t)(bi * T) * NN + (size_t)(bj * T), g, c4, pol);
    if (!diag)
        load_tile(s2a, adj + (size_t)(bj * T) * NN + (size_t)(bi * T), g, c4, pol);
    cp_commit();
    cp_wait0();
    __syncthreads();

    int ca = c4 ^ (g & 7);      // s1 row-patch physical chunk
    int gb = g ^ (c4 & 7);      // transposed-patch physical chunk

    float a[4][4], b[4][4];
    #pragma unroll
    for (int i = 0; i < 4; i++)
        *(float4*)a[i] = *(const float4*)(s1 + (4 * g + i) * 64 + 4 * ca);
    const float* sB = diag ? s1 : s2;
    #pragma unroll
    for (int e = 0; e < 4; e++)
        *(float4*)b[e] = *(const float4*)(sB + (4 * c4 + e) * 64 + 4 * gb);

    float w[4][4];
    float rs[4] = {0, 0, 0, 0}, cs[4] = {0, 0, 0, 0};
    #pragma unroll
    for (int i = 0; i < 4; i++)
        #pragma unroll
        for (int e = 0; e < 4; e++) {
            float v = fmaxf(a[i][e], b[e][i]);
            w[i][e] = v;
            rs[i] += v;
            cs[e] += v;
        }

    // Persist m tile as fp16 (normal stores -> L2-resident for pass2).
    __half* mt = g_m + (size_t)t * (T * T);
    #pragma unroll
    for (int i = 0; i < 4; i++) {
        __half2 h0 = __floats2half2_rn(w[i][0], w[i][1]);
        __half2 h1 = __floats2half2_rn(w[i][2], w[i][3]);
        uint2 pk;
        pk.x = *(uint32_t*)&h0;
        pk.y = *(uint32_t*)&h1;
        *(uint2*)(mt + (4 * g + i) * T + 4 * c4) = pk;
    }

    *(float4*)&rbuf[c4][4 * g] = make_float4(rs[0], rs[1], rs[2], rs[3]);
    *(float4*)&cbuf[g][4 * c4] = make_float4(cs[0], cs[1], cs[2], cs[3]);
    __syncthreads();

    if (tid < T) {
        float s = 0.0f;
        #pragma unroll
        for (int k = 0; k < 16; k++) s += rbuf[k][tid];
        g_part[bj][bi * T + tid] = s;            // rows of block bi
    } else if (!diag && tid < 2 * T) {
        int u = tid - T;
        float s = 0.0f;
        #pragma unroll
        for (int k = 0; k < 16; k++) s += cbuf[k][u];
        g_part[bi][bj * T + u] = s;              // rows of block bj
    }
}

// ---------------------------------------------------------------------------
// d[i] = (1 + sum_k part[k][i])^-1/2   (rowsum >= 1, never inf)
// g_part reads use __ldcs: read-once, don't evict m from L2.
// ---------------------------------------------------------------------------
__global__ __launch_bounds__(256) void reduce_d_kernel() {
    int i4 = blockIdx.x * blockDim.x + threadIdx.x;   // float4 index
    float4 s = make_float4(1.0f, 1.0f, 1.0f, 1.0f);   // self-loops
    #pragma unroll 4
    for (int k = 0; k < NT; k++) {
        float4 p = __ldcs((const float4*)&g_part[k][4 * i4]);
        s.x += p.x; s.y += p.y; s.z += p.z; s.w += p.w;
    }
    float4 d = make_float4(rsqrtf(s.x), rsqrtf(s.y), rsqrtf(s.z), rsqrtf(s.w));
    *(float4*)&g_d[4 * i4] = d;
}

// ---------------------------------------------------------------------------
// Pass 2: out = d[i]*d[j]*(m + I). NO shared memory, NO barrier.
// Upper tile: straight m-patch read + coalesced __stcs.
// Lower tile: re-read m transposed (L2 hits; 4-lane 32B-sector coalescing)
//             and write coalesced __stcs directly — no staging.
// LIFO tile order keeps g_m L2-resident.
// ---------------------------------------------------------------------------
__global__ __launch_bounds__(256) void pass2_kernel(float* __restrict__ out) {
    int t = NPAIRS - 1 - blockIdx.x;   // LIFO vs pass1 writes
    int bi, bj;
    tri_decode(t, bi, bj);
    int tid = threadIdx.x;
    int c4 = tid & 15, g = tid >> 4;
    bool diag = (bi == bj);

    const __half* mt = g_m + (size_t)t * (T * T);

    // ---- Section A: upper tile (rows of bi, cols of bj) ----
    {
        uint2 pk[4];
        #pragma unroll
        for (int i = 0; i < 4; i++)
            pk[i] = *(const uint2*)(mt + (4 * g + i) * T + 4 * c4);

        float dA[4], dB[4];
        #pragma unroll
        for (int i = 0; i < 4; i++) dA[i] = __ldg(&g_d[bi * T + 4 * g + i]);
        #pragma unroll
        for (int e = 0; e < 4; e++) dB[e] = __ldg(&g_d[bj * T + 4 * c4 + e]);

        float* po1 = out + (size_t)(bi * T) * NN + (size_t)(bj * T);
        #pragma unroll
        for (int i = 0; i < 4; i++) {
            __half2 h0 = *(__half2*)&pk[i].x;
            __half2 h1 = *(__half2*)&pk[i].y;
            float2 f0 = __half22float2(h0);
            float2 f1 = __half22float2(h1);
            float w0 = f0.x, w1 = f0.y, w2 = f1.x, w3 = f1.y;
            if (diag && g == c4) {
                if (i == 0) w0 += 1.0f;
                if (i == 1) w1 += 1.0f;
                if (i == 2) w2 += 1.0f;
                if (i == 3) w3 += 1.0f;
            }
            float4 o = make_float4(dA[i] * dB[0] * w0, dA[i] * dB[1] * w1,
                                   dA[i] * dB[2] * w2, dA[i] * dB[3] * w3);
            __stcs((float4*)(po1 + (size_t)(4 * g + i) * NN + 4 * c4), o);
        }
    }

    // ---- Section B: lower tile (rows of bj, cols of bi) = m transposed ----
    if (!diag) {
        // Thread owns out2 patch rows 4g..4g+3 (bj block), cols 4c4..4c4+3 (bi
        // block): out2[u][v] = d[bj*T+u] * d[bi*T+v] * m[v][u].
        // Needs m rows 4c4+e, cols 4g..4g+3: 4x 8B loads (L2 hits).
        uint2 pkT[4];
        #pragma unroll
        for (int e = 0; e < 4; e++)
            pkT[e] = *(const uint2*)(mt + (4 * c4 + e) * T + 4 * g);

        float dU[4], dV[4];
        #pragma unroll
        for (int i = 0; i < 4; i++) dU[i] = __ldg(&g_d[bj * T + 4 * g + i]);
        #pragma unroll
        for (int e = 0; e < 4; e++) dV[e] = __ldg(&g_d[bi * T + 4 * c4 + e]);

        // mT[e][i] = m[4c4+e][4g+i]
        float mT[4][4];
        #pragma unroll
        for (int e = 0; e < 4; e++) {
            __half2 h0 = *(__half2*)&pkT[e].x;
            __half2 h1 = *(__half2*)&pkT[e].y;
            float2 f0 = __half22float2(h0);
            float2 f1 = __half22float2(h1);
            mT[e][0] = f0.x; mT[e][1] = f0.y; mT[e][2] = f1.x; mT[e][3] = f1.y;
        }

        float* po2 = out + (size_t)(bj * T) * NN + (size_t)(bi * T);
        #pragma unroll
        for (int i = 0; i < 4; i++) {
            float4 o = make_float4(dU[i] * dV[0] * mT[0][i], dU[i] * dV[1] * mT[1][i],
                                   dU[i] * dV[2] * mT[2][i], dU[i] * dV[3] * mT[3][i]);
            __stcs((float4*)(po2 + (size_t)(4 * g + i) * NN + 4 * c4), o);
        }
    }
}

extern "C" void kernel_launch(void* const* d_in, const int* in_sizes, int n_in,
                              void* d_out, int out_size) {
    const float* adj = (const float*)d_in[0];
    float* out = (float*)d_out;
    (void)in_sizes; (void)n_in; (void)out_size;

    pass1_kernel<<<NPAIRS, 256>>>(adj);
    reduce_d_kernel<<<NN / 4 / 256, 256>>>();
    pass2_kernel<<<NPAIRS, 256>>>(out);
}

// round 13
// speedup vs baseline: 1.0629x; 1.0629x over previous
#include <cuda_runtime.h>
#include <cuda_fp16.h>
#include <math.h>
#include <stdint.h>

#define NN 8192
#define T 64
#define NT (NN / T)                 // 128
#define NPAIRS (NT * (NT + 1) / 2)  // 8256 upper-tri tile pairs

// 16B-granular XOR swizzle for fp32 tiles: phys_chunk = chunk ^ ((row>>2)&7).
#define SWZ(r) (((r) >> 2) & 7)

__device__ float g_part[NT][NN];          // per-slot partial rowsums (4 MB)
__device__ float g_d[NN];
__device__ __half g_m[(size_t)NPAIRS * T * T];   // fp16 m tiles, 64.5 MB

// ---------------------------------------------------------------------------
__device__ __forceinline__ void tri_decode(int t, int& bi, int& bj) {
    float a = 2.0f * NT + 1.0f;
    int b = (int)(0.5f * (a - sqrtf(a * a - 8.0f * (float)t)));
    if (b < 0) b = 0;
    if (b > NT - 1) b = NT - 1;
    while (b > 0 && (b * NT - b * (b - 1) / 2) > t) b--;
    while (((b + 1) * NT - (b + 1) * b / 2) <= t) b++;
    bi = b;
    bj = b + (t - (b * NT - b * (b - 1) / 2));
}

// cp.async with L2 evict-first policy: adj is read-once, keep it OUT of L2
// so the g_m write stream stays resident for pass2.
__device__ __forceinline__ uint64_t mk_evict_first() {
    uint64_t pol;
    asm("createpolicy.fractional.L2::evict_first.b64 %0, 1.0;" : "=l"(pol));
    return pol;
}
__device__ __forceinline__ void cp_async16_ef(uint32_t dst, const float* src, uint64_t pol) {
    asm volatile("cp.async.cg.shared.global.L2::cache_hint [%0], [%1], 16, %2;"
                 :: "r"(dst), "l"(src), "l"(pol));
}
__device__ __forceinline__ void cp_commit() {
    asm volatile("cp.async.commit_group;" ::: "memory");
}
__device__ __forceinline__ void cp_wait0() {
    asm volatile("cp.async.wait_group 0;" ::: "memory");
}

// Issue one 64x64 fp32 tile load: thread (g = tid>>4, c4 = tid&15) loads 4 rows.
__device__ __forceinline__ void load_tile(uint32_t sbase, const float* __restrict__ src,
                                          int g, int c4, uint64_t pol) {
    #pragma unroll
    for (int k = 0; k < 4; k++) {
        int row = g + 16 * k;
        uint32_t dst = sbase + (uint32_t)((row * 64 + 4 * (c4 ^ SWZ(row))) * 4);
        cp_async16_ef(dst, src + (size_t)row * NN + 4 * c4, pol);
    }
}

// ---------------------------------------------------------------------------
// Pass 1 (identical to R9 best): m = max(adj, adjT); fp32 row+col partials;
// persist m as fp16 (normal stores, stays L2-resident); adj evict-first.
// ---------------------------------------------------------------------------
__global__ __launch_bounds__(256) void pass1_kernel(const float* __restrict__ adj) {
    __shared__ float s1[T * T];
    __shared__ float s2[T * T];
    __shared__ float rbuf[16][68];   // rbuf[c4][row]
    __shared__ float cbuf[16][68];   // cbuf[g][col]

    int t = blockIdx.x;
    int bi, bj;
    tri_decode(t, bi, bj);
    int tid = threadIdx.x;
    int c4 = tid & 15, g = tid >> 4;
    bool diag = (bi == bj);
    uint64_t pol = mk_evict_first();

    uint32_t s1a = (uint32_t)__cvta_generic_to_shared(s1);
    uint32_t s2a = (uint32_t)__cvta_generic_to_shared(s2);

    load_tile(s1a, adj + (size_t)(bi * T) * NN + (size_t)(bj * T), g, c4, pol);
    if (!diag)
        load_tile(s2a, adj + (size_t)(bj * T) * NN + (size_t)(bi * T), g, c4, pol);
    cp_commit();
    cp_wait0();
    __syncthreads();

    int ca = c4 ^ (g & 7);      // s1 row-patch physical chunk
    int gb = g ^ (c4 & 7);      // transposed-patch physical chunk

    float a[4][4], b[4][4];
    #pragma unroll
    for (int i = 0; i < 4; i++)
        *(float4*)a[i] = *(const float4*)(s1 + (4 * g + i) * 64 + 4 * ca);
    const float* sB = diag ? s1 : s2;
    #pragma unroll
    for (int e = 0; e < 4; e++)
        *(float4*)b[e] = *(const float4*)(sB + (4 * c4 + e) * 64 + 4 * gb);

    float w[4][4];
    float rs[4] = {0, 0, 0, 0}, cs[4] = {0, 0, 0, 0};
    #pragma unroll
    for (int i = 0; i < 4; i++)
        #pragma unroll
        for (int e = 0; e < 4; e++) {
            float v = fmaxf(a[i][e], b[e][i]);
            w[i][e] = v;
            rs[i] += v;
            cs[e] += v;
        }

    // Persist m tile as fp16 (normal stores -> L2-resident for pass2).
    __half* mt = g_m + (size_t)t * (T * T);
    #pragma unroll
    for (int i = 0; i < 4; i++) {
        __half2 h0 = __floats2half2_rn(w[i][0], w[i][1]);
        __half2 h1 = __floats2half2_rn(w[i][2], w[i][3]);
        uint2 pk;
        pk.x = *(uint32_t*)&h0;
        pk.y = *(uint32_t*)&h1;
        *(uint2*)(mt + (4 * g + i) * T + 4 * c4) = pk;
    }

    *(float4*)&rbuf[c4][4 * g] = make_float4(rs[0], rs[1], rs[2], rs[3]);
    *(float4*)&cbuf[g][4 * c4] = make_float4(cs[0], cs[1], cs[2], cs[3]);
    __syncthreads();

    if (tid < T) {
        float s = 0.0f;
        #pragma unroll
        for (int k = 0; k < 16; k++) s += rbuf[k][tid];
        g_part[bj][bi * T + tid] = s;            // rows of block bi
    } else if (!diag && tid < 2 * T) {
        int u = tid - T;
        float s = 0.0f;
        #pragma unroll
        for (int k = 0; k < 16; k++) s += cbuf[k][u];
        g_part[bi][bj * T + u] = s;              // rows of block bj
    }
}

// ---------------------------------------------------------------------------
// d[i] = (1 + sum_k part[k][i])^-1/2   (rowsum >= 1, never inf)
// g_part reads use __ldcs: read-once, don't evict m from L2.
// ---------------------------------------------------------------------------
__global__ __launch_bounds__(256) void reduce_d_kernel() {
    int i4 = blockIdx.x * blockDim.x + threadIdx.x;   // float4 index
    float4 s = make_float4(1.0f, 1.0f, 1.0f, 1.0f);   // self-loops
    #pragma unroll 4
    for (int k = 0; k < NT; k++) {
        float4 p = __ldcs((const float4*)&g_part[k][4 * i4]);
        s.x += p.x; s.y += p.y; s.z += p.z; s.w += p.w;
    }
    float4 d = make_float4(rsqrtf(s.x), rsqrtf(s.y), rsqrtf(s.z), rsqrtf(s.w));
    *(float4*)&g_d[4 * i4] = d;
}

// ---------------------------------------------------------------------------
// Pass 2: one output tile per block, grid (bj fastest) => concurrent blocks
// write ADJACENT tiles along the same 64 rows: near-sequential DRAM write
// stream. Upper blocks read m straight; lower blocks read the mirror tile
// and transpose via swizzled smem (one barrier). All m traffic is L2.
// ---------------------------------------------------------------------------
__global__ __launch_bounds__(256) void pass2_kernel(float* __restrict__ out) {
    __shared__ float st[T * T];      // transpose staging (swizzled)

    int bj = blockIdx.x;             // col tile — fastest: row-sequential writes
    int bi = NT - 1 - blockIdx.y;    // row tile — reversed for m recency in L2
    int tid = threadIdx.x;
    int c4 = tid & 15, g = tid >> 4;

    bool upper = (bi <= bj);
    int ti = upper ? bi : bj;
    int tj = upper ? bj : bi;
    int t = ti * NT - (ti * (ti - 1)) / 2 + (tj - ti);   // pair index
    const __half* mt = g_m + (size_t)t * (T * T);

    // Load straight patch of the stored tile: rows 4g+i, cols 4c4.. (coalesced 8B)
    uint2 pk[4];
    #pragma unroll
    for (int i = 0; i < 4; i++)
        pk[i] = *(const uint2*)(mt + (4 * g + i) * T + 4 * c4);

    float dA[4], dB[4];
    #pragma unroll
    for (int i = 0; i < 4; i++) dA[i] = __ldg(&g_d[bi * T + 4 * g + i]);
    #pragma unroll
    for (int e = 0; e < 4; e++) dB[e] = __ldg(&g_d[bj * T + 4 * c4 + e]);

    float w[4][4];
    if (upper) {
        // w[i][e] = mt[4g+i][4c4+e]
        #pragma unroll
        for (int i = 0; i < 4; i++) {
            __half2 h0 = *(__half2*)&pk[i].x;
            __half2 h1 = *(__half2*)&pk[i].y;
            float2 f0 = __half22float2(h0);
            float2 f1 = __half22float2(h1);
            w[i][0] = f0.x; w[i][1] = f0.y; w[i][2] = f1.x; w[i][3] = f1.y;
        }
        if (bi == bj && g == c4) {
            #pragma unroll
            for (int i = 0; i < 4; i++) w[i][i] += 1.0f;
        }
    } else {
        // Need mt transposed: out[u][v] = mt[v][u]. Stage straight patch into
        // swizzled smem, then read the transposed patch (both conflict-free).
        int ca = c4 ^ (g & 7);       // SWZ(4g+i) == g&7 for i in 0..3
        int gb = g ^ (c4 & 7);
        #pragma unroll
        for (int i = 0; i < 4; i++) {
            __half2 h0 = *(__half2*)&pk[i].x;
            __half2 h1 = *(__half2*)&pk[i].y;
            float2 f0 = __half22float2(h0);
            float2 f1 = __half22float2(h1);
            *(float4*)(st + (4 * g + i) * 64 + 4 * ca) =
                make_float4(f0.x, f0.y, f1.x, f1.y);
        }
        __syncthreads();
        // w[i][e] = mt[4c4+e][4g+i] read as transposed-patch LDS.128
        float bT[4][4];
        #pragma unroll
        for (int e = 0; e < 4; e++)
            *(float4*)bT[e] = *(const float4*)(st + (4 * c4 + e) * 64 + 4 * gb);
        #pragma unroll
        for (int i = 0; i < 4; i++)
            #pragma unroll
            for (int e = 0; e < 4; e++)
                w[i][e] = bT[e][i];
    }

    // Scale and store: coalesced streaming STG.128, row-sequential across blocks.
    float* po = out + (size_t)(bi * T) * NN + (size_t)(bj * T);
    #pragma unroll
    for (int i = 0; i < 4; i++) {
        float4 o = make_float4(dA[i] * dB[0] * w[i][0], dA[i] * dB[1] * w[i][1],
                               dA[i] * dB[2] * w[i][2], dA[i] * dB[3] * w[i][3]);
        __stcs((float4*)(po + (size_t)(4 * g + i) * NN + 4 * c4), o);
    }
}

extern "C" void kernel_launch(void* const* d_in, const int* in_sizes, int n_in,
                              void* d_out, int out_size) {
    const float* adj = (const float*)d_in[0];
    float* out = (float*)d_out;
    (void)in_sizes; (void)n_in; (void)out_size;

    pass1_kernel<<<NPAIRS, 256>>>(adj);
    reduce_d_kernel<<<NN / 4 / 256, 256>>>();
    pass2_kernel<<<dim3(NT, NT), 256>>>(out);
}

// round 14
// speedup vs baseline: 1.0641x; 1.0011x over previous
#include <cuda_runtime.h>
#include <cuda_fp16.h>
#include <math.h>
#include <stdint.h>

#define NN 8192
#define T 64
#define NT (NN / T)                 // 128
#define NPAIRS (NT * (NT + 1) / 2)  // 8256 upper-tri tile pairs

// 16B-granular XOR swizzle for fp32 tiles: phys_chunk = chunk ^ ((row>>2)&7).
#define SWZ(r) (((r) >> 2) & 7)

__device__ float g_part[NT][NN];          // per-slot partial rowsums (4 MB)
__device__ float g_d[NN];
__device__ __half g_m[(size_t)NPAIRS * T * T];   // fp16 m tiles, 64.5 MB

// ---------------------------------------------------------------------------
__device__ __forceinline__ void tri_decode(int t, int& bi, int& bj) {
    float a = 2.0f * NT + 1.0f;
    int b = (int)(0.5f * (a - sqrtf(a * a - 8.0f * (float)t)));
    if (b < 0) b = 0;
    if (b > NT - 1) b = NT - 1;
    while (b > 0 && (b * NT - b * (b - 1) / 2) > t) b--;
    while (((b + 1) * NT - (b + 1) * b / 2) <= t) b++;
    bi = b;
    bj = b + (t - (b * NT - b * (b - 1) / 2));
}

// cp.async with L2 evict-first policy: adj is read-once, keep it OUT of L2
// so the g_m write stream stays resident for pass2.
__device__ __forceinline__ uint64_t mk_evict_first() {
    uint64_t pol;
    asm("createpolicy.fractional.L2::evict_first.b64 %0, 1.0;" : "=l"(pol));
    return pol;
}
__device__ __forceinline__ void cp_async16_ef(uint32_t dst, const float* src, uint64_t pol) {
    asm volatile("cp.async.cg.shared.global.L2::cache_hint [%0], [%1], 16, %2;"
                 :: "r"(dst), "l"(src), "l"(pol));
}
__device__ __forceinline__ void cp_commit() {
    asm volatile("cp.async.commit_group;" ::: "memory");
}
__device__ __forceinline__ void cp_wait0() {
    asm volatile("cp.async.wait_group 0;" ::: "memory");
}

// Issue one 64x64 fp32 tile load: thread (g = tid>>4, c4 = tid&15) loads 4 rows.
__device__ __forceinline__ void load_tile(uint32_t sbase, const float* __restrict__ src,
                                          int g, int c4, uint64_t pol) {
    #pragma unroll
    for (int k = 0; k < 4; k++) {
        int row = g + 16 * k;
        uint32_t dst = sbase + (uint32_t)((row * 64 + 4 * (c4 ^ SWZ(row))) * 4);
        cp_async16_ef(dst, src + (size_t)row * NN + 4 * c4, pol);
    }
}

// ---------------------------------------------------------------------------
// Pass 1 (identical to R9 best): m = max(adj, adjT); fp32 row+col partials;
// persist m as fp16 (normal stores, stays L2-resident); adj evict-first.
// ---------------------------------------------------------------------------
__global__ __launch_bounds__(256) void pass1_kernel(const float* __restrict__ adj) {
    __shared__ float s1[T * T];
    __shared__ float s2[T * T];
    __shared__ float rbuf[16][68];   // rbuf[c4][row]
    __shared__ float cbuf[16][68];   // cbuf[g][col]

    int t = blockIdx.x;
    int bi, bj;
    tri_decode(t, bi, bj);
    int tid = threadIdx.x;
    int c4 = tid & 15, g = tid >> 4;
    bool diag = (bi == bj);
    uint64_t pol = mk_evict_first();

    uint32_t s1a = (uint32_t)__cvta_generic_to_shared(s1);
    uint32_t s2a = (uint32_t)__cvta_generic_to_shared(s2);

    load_tile(s1a, adj + (size_t)(bi * T) * NN + (size_t)(bj * T), g, c4, pol);
    if (!diag)
        load_tile(s2a, adj + (size_t)(bj * T) * NN + (size_t)(bi * T), g, c4, pol);
    cp_commit();
    cp_wait0();
    __syncthreads();

    int ca = c4 ^ (g & 7);      // s1 row-patch physical chunk
    int gb = g ^ (c4 & 7);      // transposed-patch physical chunk

    float a[4][4], b[4][4];
    #pragma unroll
    for (int i = 0; i < 4; i++)
        *(float4*)a[i] = *(const float4*)(s1 + (4 * g + i) * 64 + 4 * ca);
    const float* sB = diag ? s1 : s2;
    #pragma unroll
    for (int e = 0; e < 4; e++)
        *(float4*)b[e] = *(const float4*)(sB + (4 * c4 + e) * 64 + 4 * gb);

    float w[4][4];
    float rs[4] = {0, 0, 0, 0}, cs[4] = {0, 0, 0, 0};
    #pragma unroll
    for (int i = 0; i < 4; i++)
        #pragma unroll
        for (int e = 0; e < 4; e++) {
            float v = fmaxf(a[i][e], b[e][i]);
            w[i][e] = v;
            rs[i] += v;
            cs[e] += v;
        }

    // Persist m tile as fp16 (normal stores -> L2-resident for pass2).
    __half* mt = g_m + (size_t)t * (T * T);
    #pragma unroll
    for (int i = 0; i < 4; i++) {
        __half2 h0 = __floats2half2_rn(w[i][0], w[i][1]);
        __half2 h1 = __floats2half2_rn(w[i][2], w[i][3]);
        uint2 pk;
        pk.x = *(uint32_t*)&h0;
        pk.y = *(uint32_t*)&h1;
        *(uint2*)(mt + (4 * g + i) * T + 4 * c4) = pk;
    }

    *(float4*)&rbuf[c4][4 * g] = make_float4(rs[0], rs[1], rs[2], rs[3]);
    *(float4*)&cbuf[g][4 * c4] = make_float4(cs[0], cs[1], cs[2], cs[3]);
    __syncthreads();

    if (tid < T) {
        float s = 0.0f;
        #pragma unroll
        for (int k = 0; k < 16; k++) s += rbuf[k][tid];
        g_part[bj][bi * T + tid] = s;            // rows of block bi
    } else if (!diag && tid < 2 * T) {
        int u = tid - T;
        float s = 0.0f;
        #pragma unroll
        for (int k = 0; k < 16; k++) s += cbuf[k][u];
        g_part[bi][bj * T + u] = s;              // rows of block bj
    }
}

// ---------------------------------------------------------------------------
// d[i] = (1 + sum_k part[k][i])^-1/2   (rowsum >= 1, never inf)
// g_part reads use __ldcs: read-once, don't evict m from L2.
// ---------------------------------------------------------------------------
__global__ __launch_bounds__(256) void reduce_d_kernel() {
    int i4 = blockIdx.x * blockDim.x + threadIdx.x;   // float4 index
    float4 s = make_float4(1.0f, 1.0f, 1.0f, 1.0f);   // self-loops
    #pragma unroll 4
    for (int k = 0; k < NT; k++) {
        float4 p = __ldcs((const float4*)&g_part[k][4 * i4]);
        s.x += p.x; s.y += p.y; s.z += p.z; s.w += p.w;
    }
    float4 d = make_float4(rsqrtf(s.x), rsqrtf(s.y), rsqrtf(s.z), rsqrtf(s.w));
    *(float4*)&g_d[4 * i4] = d;
}

// ---------------------------------------------------------------------------
// Pass 2: one output tile per block, grid (bj fastest) => concurrent blocks
// write ADJACENT tiles along the same 64 rows: near-sequential DRAM write
// stream. Upper blocks read m straight; lower blocks read the mirror tile
// and transpose via swizzled smem (one barrier). All m traffic is L2.
// ---------------------------------------------------------------------------
__global__ __launch_bounds__(256) void pass2_kernel(float* __restrict__ out) {
    __shared__ float st[T * T];      // transpose staging (swizzled)

    int bj = blockIdx.x;             // col tile — fastest: row-sequential writes
    int bi = NT - 1 - blockIdx.y;    // row tile — reversed for m recency in L2
    int tid = threadIdx.x;
    int c4 = tid & 15, g = tid >> 4;

    bool upper = (bi <= bj);
    int ti = upper ? bi : bj;
    int tj = upper ? bj : bi;
    int t = ti * NT - (ti * (ti - 1)) / 2 + (tj - ti);   // pair index
    const __half* mt = g_m + (size_t)t * (T * T);

    // Load straight patch of the stored tile: rows 4g+i, cols 4c4.. (coalesced 8B)
    uint2 pk[4];
    #pragma unroll
    for (int i = 0; i < 4; i++)
        pk[i] = *(const uint2*)(mt + (4 * g + i) * T + 4 * c4);

    float dA[4], dB[4];
    #pragma unroll
    for (int i = 0; i < 4; i++) dA[i] = __ldg(&g_d[bi * T + 4 * g + i]);
    #pragma unroll
    for (int e = 0; e < 4; e++) dB[e] = __ldg(&g_d[bj * T + 4 * c4 + e]);

    float w[4][4];
    if (upper) {
        // w[i][e] = mt[4g+i][4c4+e]
        #pragma unroll
        for (int i = 0; i < 4; i++) {
            __half2 h0 = *(__half2*)&pk[i].x;
            __half2 h1 = *(__half2*)&pk[i].y;
            float2 f0 = __half22float2(h0);
            float2 f1 = __half22float2(h1);
            w[i][0] = f0.x; w[i][1] = f0.y; w[i][2] = f1.x; w[i][3] = f1.y;
        }
        if (bi == bj && g == c4) {
            #pragma unroll
            for (int i = 0; i < 4; i++) w[i][i] += 1.0f;
        }
    } else {
        // Need mt transposed: out[u][v] = mt[v][u]. Stage straight patch into
        // swizzled smem, then read the transposed patch (both conflict-free).
        int ca = c4 ^ (g & 7);       // SWZ(4g+i) == g&7 for i in 0..3
        int gb = g ^ (c4 & 7);
        #pragma unroll
        for (int i = 0; i < 4; i++) {
            __half2 h0 = *(__half2*)&pk[i].x;
            __half2 h1 = *(__half2*)&pk[i].y;
            float2 f0 = __half22float2(h0);
            float2 f1 = __half22float2(h1);
            *(float4*)(st + (4 * g + i) * 64 + 4 * ca) =
                make_float4(f0.x, f0.y, f1.x, f1.y);
        }
        __syncthreads();
        // w[i][e] = mt[4c4+e][4g+i] read as transposed-patch LDS.128
        float bT[4][4];
        #pragma unroll
        for (int e = 0; e < 4; e++)
            *(float4*)bT[e] = *(const float4*)(st + (4 * c4 + e) * 64 + 4 * gb);
        #pragma unroll
        for (int i = 0; i < 4; i++)
            #pragma unroll
            for (int e = 0; e < 4; e++)
                w[i][e] = bT[e][i];
    }

    // Scale and store: coalesced streaming STG.128, row-sequential across blocks.
    float* po = out + (size_t)(bi * T) * NN + (size_t)(bj * T);
    #pragma unroll
    for (int i = 0; i < 4; i++) {
        float4 o = make_float4(dA[i] * dB[0] * w[i][0], dA[i] * dB[1] * w[i][1],
                               dA[i] * dB[2] * w[i][2], dA[i] * dB[3] * w[i][3]);
        __stcs((float4*)(po + (size_t)(4 * g + i) * NN + 4 * c4), o);
    }
}

extern "C" void kernel_launch(void* const* d_in, const int* in_sizes, int n_in,
                              void* d_out, int out_size) {
    const float* adj = (const float*)d_in[0];
    float* out = (float*)d_out;
    (void)in_sizes; (void)n_in; (void)out_size;

    pass1_kernel<<<NPAIRS, 256>>>(adj);
    reduce_d_kernel<<<NN / 4 / 256, 256>>>();
    pass2_kernel<<<dim3(NT, NT), 256>>>(out);
}

// round 15
// speedup vs baseline: 1.1382x; 1.0697x over previous
#include <cuda_runtime.h>
#include <cuda_fp16.h>
#include <math.h>
#include <stdint.h>

#define NN 8192
#define T 64
#define NT (NN / T)                 // 128
#define NPAIRS (NT * (NT + 1) / 2)  // 8256 upper-tri tile pairs

// 16B-granular XOR swizzle for fp32 tiles: phys_chunk = chunk ^ ((row>>2)&7).
#define SWZ(r) (((r) >> 2) & 7)

__device__ float g_part[NT][NN];          // per-slot partial rowsums (4 MB)
__device__ float g_d[NN];
__device__ __half g_m[(size_t)NPAIRS * T * T];   // fp16 m tiles, 64.5 MB

// ---------------------------------------------------------------------------
__device__ __forceinline__ void tri_decode(int t, int& bi, int& bj) {
    float a = 2.0f * NT + 1.0f;
    int b = (int)(0.5f * (a - sqrtf(a * a - 8.0f * (float)t)));
    if (b < 0) b = 0;
    if (b > NT - 1) b = NT - 1;
    while (b > 0 && (b * NT - b * (b - 1) / 2) > t) b--;
    while (((b + 1) * NT - (b + 1) * b / 2) <= t) b++;
    bi = b;
    bj = b + (t - (b * NT - b * (b - 1) / 2));
}

// cp.async with L2 evict-first policy: adj is read-once, keep it OUT of L2
// so the g_m write stream stays resident for pass2.
__device__ __forceinline__ uint64_t mk_evict_first() {
    uint64_t pol;
    asm("createpolicy.fractional.L2::evict_first.b64 %0, 1.0;" : "=l"(pol));
    return pol;
}
__device__ __forceinline__ void cp_async16_ef(uint32_t dst, const float* src, uint64_t pol) {
    asm volatile("cp.async.cg.shared.global.L2::cache_hint [%0], [%1], 16, %2;"
                 :: "r"(dst), "l"(src), "l"(pol));
}
__device__ __forceinline__ void cp_commit() {
    asm volatile("cp.async.commit_group;" ::: "memory");
}
__device__ __forceinline__ void cp_wait0() {
    asm volatile("cp.async.wait_group 0;" ::: "memory");
}

// Issue one 64x64 fp32 tile load: thread (g = tid>>4, c4 = tid&15) loads 4 rows.
__device__ __forceinline__ void load_tile(uint32_t sbase, const float* __restrict__ src,
                                          int g, int c4, uint64_t pol) {
    #pragma unroll
    for (int k = 0; k < 4; k++) {
        int row = g + 16 * k;
        uint32_t dst = sbase + (uint32_t)((row * 64 + 4 * (c4 ^ SWZ(row))) * 4);
        cp_async16_ef(dst, src + (size_t)row * NN + 4 * c4, pol);
    }
}

// ---------------------------------------------------------------------------
// Pass 1 (identical to R9 best): m = max(adj, adjT); fp32 row+col partials;
// persist m as fp16 (normal stores, stays L2-resident); adj evict-first.
// ---------------------------------------------------------------------------
__global__ __launch_bounds__(256) void pass1_kernel(const float* __restrict__ adj) {
    __shared__ float s1[T * T];
    __shared__ float s2[T * T];
    __shared__ float rbuf[16][68];   // rbuf[c4][row]
    __shared__ float cbuf[16][68];   // cbuf[g][col]

    int t = blockIdx.x;
    int bi, bj;
    tri_decode(t, bi, bj);
    int tid = threadIdx.x;
    int c4 = tid & 15, g = tid >> 4;
    bool diag = (bi == bj);
    uint64_t pol = mk_evict_first();

    uint32_t s1a = (uint32_t)__cvta_generic_to_shared(s1);
    uint32_t s2a = (uint32_t)__cvta_generic_to_shared(s2);

    load_tile(s1a, adj + (size_t)(bi * T) * NN + (size_t)(bj * T), g, c4, pol);
    if (!diag)
        load_tile(s2a, adj + (size_t)(bj * T) * NN + (size_t)(bi * T), g, c4, pol);
    cp_commit();
    cp_wait0();
    __syncthreads();

    int ca = c4 ^ (g & 7);      // s1 row-patch physical chunk
    int gb = g ^ (c4 & 7);      // transposed-patch physical chunk

    float a[4][4], b[4][4];
    #pragma unroll
    for (int i = 0; i < 4; i++)
        *(float4*)a[i] = *(const float4*)(s1 + (4 * g + i) * 64 + 4 * ca);
    const float* sB = diag ? s1 : s2;
    #pragma unroll
    for (int e = 0; e < 4; e++)
        *(float4*)b[e] = *(const float4*)(sB + (4 * c4 + e) * 64 + 4 * gb);

    float w[4][4];
    float rs[4] = {0, 0, 0, 0}, cs[4] = {0, 0, 0, 0};
    #pragma unroll
    for (int i = 0; i < 4; i++)
        #pragma unroll
        for (int e = 0; e < 4; e++) {
            float v = fmaxf(a[i][e], b[e][i]);
            w[i][e] = v;
            rs[i] += v;
            cs[e] += v;
        }

    // Persist m tile as fp16 (normal stores -> L2-resident for pass2).
    __half* mt = g_m + (size_t)t * (T * T);
    #pragma unroll
    for (int i = 0; i < 4; i++) {
        __half2 h0 = __floats2half2_rn(w[i][0], w[i][1]);
        __half2 h1 = __floats2half2_rn(w[i][2], w[i][3]);
        uint2 pk;
        pk.x = *(uint32_t*)&h0;
        pk.y = *(uint32_t*)&h1;
        *(uint2*)(mt + (4 * g + i) * T + 4 * c4) = pk;
    }

    *(float4*)&rbuf[c4][4 * g] = make_float4(rs[0], rs[1], rs[2], rs[3]);
    *(float4*)&cbuf[g][4 * c4] = make_float4(cs[0], cs[1], cs[2], cs[3]);
    __syncthreads();

    if (tid < T) {
        float s = 0.0f;
        #pragma unroll
        for (int k = 0; k < 16; k++) s += rbuf[k][tid];
        g_part[bj][bi * T + tid] = s;            // rows of block bi
    } else if (!diag && tid < 2 * T) {
        int u = tid - T;
        float s = 0.0f;
        #pragma unroll
        for (int k = 0; k < 16; k++) s += cbuf[k][u];
        g_part[bi][bj * T + u] = s;              // rows of block bj
    }
}

// ---------------------------------------------------------------------------
// d[i] = (1 + sum_k part[k][i])^-1/2   (rowsum >= 1, never inf)
// g_part reads use __ldcs: read-once, don't evict m from L2.
// ---------------------------------------------------------------------------
__global__ __launch_bounds__(256) void reduce_d_kernel() {
    int i4 = blockIdx.x * blockDim.x + threadIdx.x;   // float4 index
    float4 s = make_float4(1.0f, 1.0f, 1.0f, 1.0f);   // self-loops
    #pragma unroll 4
    for (int k = 0; k < NT; k++) {
        float4 p = __ldcs((const float4*)&g_part[k][4 * i4]);
        s.x += p.x; s.y += p.y; s.z += p.z; s.w += p.w;
    }
    float4 d = make_float4(rsqrtf(s.x), rsqrtf(s.y), rsqrtf(s.z), rsqrtf(s.w));
    *(float4*)&g_d[4 * i4] = d;
}

// ---------------------------------------------------------------------------
// Pass 2 (R9 best + L2 discard): out = d[i]*d[j]*(m + I). m read once from
// L2 (LIFO order), then the tile's dirty lines are DISCARDED — they are never
// written back to DRAM. Out written with streaming stores.
// ---------------------------------------------------------------------------
__global__ __launch_bounds__(256) void pass2_kernel(float* __restrict__ out) {
    __shared__ float st[T * T];      // transposed-output staging (swizzled)

    int t = NPAIRS - 1 - blockIdx.x;   // LIFO vs pass1 writes
    int bi, bj;
    tri_decode(t, bi, bj);
    int tid = threadIdx.x;
    int c4 = tid & 15, g = tid >> 4;
    bool diag = (bi == bj);

    // Issue m loads first.
    const __half* mt = g_m + (size_t)t * (T * T);
    uint2 pk[4];
    #pragma unroll
    for (int i = 0; i < 4; i++)
        pk[i] = *(const uint2*)(mt + (4 * g + i) * T + 4 * c4);

    // d factors: broadcast loads, L1/L2-resident (32 KB vector).
    float dA[4], dB[4];
    #pragma unroll
    for (int i = 0; i < 4; i++) dA[i] = __ldg(&g_d[bi * T + 4 * g + i]);
    #pragma unroll
    for (int e = 0; e < 4; e++) dB[e] = __ldg(&g_d[bj * T + 4 * c4 + e]);

    float w[4][4];
    #pragma unroll
    for (int i = 0; i < 4; i++) {
        __half2 h0 = *(__half2*)&pk[i].x;
        __half2 h1 = *(__half2*)&pk[i].y;
        float2 f0 = __half22float2(h0);
        float2 f1 = __half22float2(h1);
        w[i][0] = f0.x; w[i][1] = f0.y; w[i][2] = f1.x; w[i][3] = f1.y;
    }

    #pragma unroll
    for (int i = 0; i < 4; i++)
        #pragma unroll
        for (int e = 0; e < 4; e++) {
            float v = w[i][e];
            if (diag && g == c4 && i == e) v += 1.0f;
            w[i][e] = dA[i] * dB[e] * v;
        }

    // Upper output tile (rows of block bi): coalesced streaming STG.128
    float* po1 = out + (size_t)(bi * T) * NN + (size_t)(bj * T);
    #pragma unroll
    for (int i = 0; i < 4; i++)
        __stcs((float4*)(po1 + (size_t)(4 * g + i) * NN + 4 * c4), *(float4*)w[i]);

    if (!diag) {
        // Lower tile = w transposed: stage through swizzled smem, write coalesced.
        int ca = c4 ^ (g & 7);
        int gb = g ^ (c4 & 7);
        #pragma unroll
        for (int e = 0; e < 4; e++)
            *(float4*)(st + (4 * c4 + e) * 64 + 4 * gb) =
                make_float4(w[0][e], w[1][e], w[2][e], w[3][e]);
        __syncthreads();

        float* po2 = out + (size_t)(bj * T) * NN + (size_t)(bi * T);
        #pragma unroll
        for (int i = 0; i < 4; i++) {
            float4 o = *(const float4*)(st + (4 * g + i) * 64 + 4 * ca);
            __stcs((float4*)(po2 + (size_t)(4 * g + i) * NN + 4 * c4), o);
        }
    } else {
        __syncthreads();   // align with non-diag path: all m reads consumed
    }

    // Discard this block's m tile from L2 — dirty lines are dropped without
    // DRAM write-back. Tile is block-private in pass2 (read exactly once) and
    // fully rewritten by pass1 on every replay, so this is safe + deterministic.
    // 8192 B = 64 lines of 128 B; threads 0..63 each discard one line.
    if (tid < 64) {
        const __half* line = mt + tid * 64;   // 64 halves = 128 B
        asm volatile("discard.global.L2 [%0], 128;" :: "l"(line) : "memory");
    }
}

extern "C" void kernel_launch(void* const* d_in, const int* in_sizes, int n_in,
                              void* d_out, int out_size) {
    const float* adj = (const float*)d_in[0];
    float* out = (float*)d_out;
    (void)in_sizes; (void)n_in; (void)out_size;

    pass1_kernel<<<NPAIRS, 256>>>(adj);
    reduce_d_kernel<<<NN / 4 / 256, 256>>>();
    pass2_kernel<<<NPAIRS, 256>>>(out);
}